// round 16
// baseline (speedup 1.0000x reference)
#include <cuda_runtime.h>
#include <math.h>
#include <stdint.h>
#include <string.h>

#define BSZ   8
#define SEQ   19947
#define MROWS 159576          // BSZ*SEQ
#define CH    256
#define NC    91
#define NCP   96              // padded cls width
#define NTOP  20
#define CHUNKS 16
#define CHUNK  1247           // ceil(SEQ/16); last chunk = 1242

// output layout (float32, concatenated flattened tuple)
#define OFF_OUT  0            // (8,20,95)
#define OFF_REF  15200        // (8,20,4)
#define OFF_KEEP 15840        // (8,20)
#define OFF_SC   16000        // (8,20)

// ---------------- scratch (device globals: allocation-free) ----------------
__device__ float g_outmem[MROWS * CH];
__device__ float g_scores[MROWS];
__device__ int   g_topidx[BSZ * NTOP];
__device__ float g_topsc[BSZ * NTOP];
__device__ float g_ctop[BSZ * NTOP * 4];
__device__ float g_toplog[BSZ * NTOP * NC];
__device__ float g_candV[BSZ * CHUNKS * NTOP];
__device__ int   g_candI[BSZ * CHUNKS * NTOP];
__device__ float g_wpad[CH * NCP];        // W_cls padded to [256][96]

// ---------------- packed f32x2 helpers (Blackwell FFMA2) -------------------
__device__ __forceinline__ unsigned long long ffma2(unsigned long long a,
                                                    unsigned long long b,
                                                    unsigned long long c)
{
    unsigned long long d;
    asm("fma.rn.f32x2 %0, %1, %2, %3;" : "=l"(d) : "l"(a), "l"(b), "l"(c));
    return d;
}
__device__ __forceinline__ unsigned long long bcast2(float x)
{
    unsigned long long d;
    unsigned int xi = __float_as_uint(x);
    asm("mov.b64 %0, {%1, %1};" : "=l"(d) : "r"(xi));
    return d;
}
__device__ __forceinline__ float pickhalf(unsigned long long v, int half)
{
    float2 p;
    memcpy(&p, &v, 8);
    return half ? p.y : p.x;
}

// row validity by geometry + mask (reference _gen_proposals semantics)
__device__ __forceinline__ bool row_valid_geom(int s)
{
    int Hh, Ww, t;
    if (s < 15000)      { Hh = 100; Ww = 150; t = s; }
    else if (s < 18750) { Hh = 50;  Ww = 75;  t = s - 15000; }
    else if (s < 19700) { Hh = 25;  Ww = 38;  t = s - 18750; }
    else                { Hh = 13;  Ww = 19;  t = s - 19700; }
    int y = t / Ww, x = t % Ww;
    float cx = ((float)x + 0.5f) / (float)Ww;
    float cy = ((float)y + 0.5f) / (float)Hh;
    return (cx > 0.01f) && (cx < 0.99f) && (cy > 0.01f) && (cy < 0.99f);
}

// ---------------- pad W_cls [256][91] -> [256][96] ---------------------------
__global__ void wpad_kernel(const float* __restrict__ Wc, float* __restrict__ Wp)
{
    int idx = blockIdx.x * 256 + threadIdx.x;
    if (idx >= CH * NCP) return;
    int k = idx / NCP, n = idx % NCP;
    Wp[idx] = (n < NC) ? Wc[k * NC + n] : 0.f;
}

// ============ FUSED: GEMM1 + bias + LayerNorm + cls rowmax ===================
// Phase A: out_mem tile = LN(mem_masked @ W_enc + b_enc)  (write Y + smem LP)
// Phase B: scores[rows] = rowmax(LP @ Wpad + b_cls)       (A never re-read)
#define GL_AS 0
#define GL_BS 4224
#define GL_RED 12416
#define LP_OFF 12928
#define GL_SMEM_FLOATS (12928 + 256 * 136)
#define GL_SMEM_BYTES (GL_SMEM_FLOATS * 4)

__global__ void __launch_bounds__(512, 1)
gemm_fused_kernel(const float* __restrict__ A, const unsigned char* __restrict__ mask,
                  const float* __restrict__ Bm, const float* __restrict__ bias,
                  const float* __restrict__ lng, const float* __restrict__ lnb,
                  const float* __restrict__ Wp, const float* __restrict__ bcls,
                  float* __restrict__ Y, float* __restrict__ scores)
{
    extern __shared__ float smf[];
    float* AsB = smf + GL_AS;     // [buf][16][132]
    float* BsB = smf + GL_BS;     // [buf][16][256]

    const int tid = threadIdx.x;
    const int warp = tid >> 5, lane = tid & 31;
    const int rowBase = blockIdx.x * 128;

    const int tRow = (warp & 3) * 32 + (lane & 3) * 8;
    const int tCol = (warp >> 2) * 64 + (lane >> 2) * 8;
    const int wcg  = warp >> 2;
    const int qA   = (warp & 3) * 4 + (lane & 3);   // pair-block id for LP writes

    const int aRow = tid >> 2, aK = (tid & 3) << 2;
    const int agr = rowBase + aRow;
    bool avalid = false;
    if (agr < MROWS) {
        int s = agr % SEQ;
        avalid = (mask[agr] == 0) && row_valid_geom(s);
    }
    const float* arow = A + (size_t)agr * CH;
    const int bK0 = tid >> 6, bN = (tid & 63) << 2, bK1 = bK0 + 8;

    unsigned long long acc2[4][8];
#pragma unroll
    for (int r = 0; r < 4; r++)
#pragma unroll
        for (int c = 0; c < 8; c++) acc2[r][c] = 0ull;

    float4 a0r = avalid ? *reinterpret_cast<const float4*>(arow + aK)
                        : make_float4(0.f, 0.f, 0.f, 0.f);
    float4 b0r = *reinterpret_cast<const float4*>(Bm + (size_t)bK0 * CH + bN);
    float4 b1r = *reinterpret_cast<const float4*>(Bm + (size_t)bK1 * CH + bN);
    AsB[(aK+0)*132 + aRow] = a0r.x; AsB[(aK+1)*132 + aRow] = a0r.y;
    AsB[(aK+2)*132 + aRow] = a0r.z; AsB[(aK+3)*132 + aRow] = a0r.w;
    *reinterpret_cast<float4*>(&BsB[bK0*256 + bN]) = b0r;
    *reinterpret_cast<float4*>(&BsB[bK1*256 + bN]) = b1r;
    __syncthreads();

#pragma unroll 1
    for (int kb = 0; kb < 16; kb++) {
        const int cur = kb & 1;
        float* As = AsB + cur * (16 * 132);
        float* Bs = BsB + cur * (16 * 256);
        if (kb < 15) {
            int k0 = (kb + 1) * 16;
            a0r = avalid ? *reinterpret_cast<const float4*>(arow + k0 + aK)
                         : make_float4(0.f, 0.f, 0.f, 0.f);
            b0r = *reinterpret_cast<const float4*>(Bm + (size_t)(k0 + bK0) * CH + bN);
            b1r = *reinterpret_cast<const float4*>(Bm + (size_t)(k0 + bK1) * CH + bN);
        }
#pragma unroll
        for (int kk = 0; kk < 16; kk++) {
            ulonglong2 a01 = *reinterpret_cast<const ulonglong2*>(&As[kk*132 + tRow]);
            ulonglong2 a23 = *reinterpret_cast<const ulonglong2*>(&As[kk*132 + tRow + 4]);
            float4 b0 = *reinterpret_cast<const float4*>(&Bs[kk*256 + tCol]);
            float4 b1 = *reinterpret_cast<const float4*>(&Bs[kk*256 + tCol + 4]);
            unsigned long long av[4] = {a01.x, a01.y, a23.x, a23.y};
            float bf[8] = {b0.x, b0.y, b0.z, b0.w, b1.x, b1.y, b1.z, b1.w};
#pragma unroll
            for (int c = 0; c < 8; c++) {
                unsigned long long bc = bcast2(bf[c]);
#pragma unroll
                for (int r = 0; r < 4; r++)
                    acc2[r][c] = ffma2(av[r], bc, acc2[r][c]);
            }
        }
        if (kb < 15) {
            float* Asn = AsB + (cur ^ 1) * (16 * 132);
            float* Bsn = BsB + (cur ^ 1) * (16 * 256);
            Asn[(aK+0)*132 + aRow] = a0r.x; Asn[(aK+1)*132 + aRow] = a0r.y;
            Asn[(aK+2)*132 + aRow] = a0r.z; Asn[(aK+3)*132 + aRow] = a0r.w;
            *reinterpret_cast<float4*>(&Bsn[bK0*256 + bN]) = b0r;
            *reinterpret_cast<float4*>(&Bsn[bK1*256 + bN]) = b1r;
            __syncthreads();
        }
    }

    // ---- phase A epilogue: bias + LayerNorm (single-pass sum/sumsq) ----
    float4 bb0 = *reinterpret_cast<const float4*>(&bias[tCol]);
    float4 bb1 = *reinterpret_cast<const float4*>(&bias[tCol + 4]);
    float bcol[8] = {bb0.x, bb0.y, bb0.z, bb0.w, bb1.x, bb1.y, bb1.z, bb1.w};

    __syncthreads();   // mainloop smem dead; reuse BsB region as float2[4][128]
    float2* red2 = reinterpret_cast<float2*>(smf + GL_BS);

#pragma unroll
    for (int r2 = 0; r2 < 4; r2++)
#pragma unroll
        for (int half = 0; half < 2; half++) {
            float ps = 0.f, qs = 0.f;
#pragma unroll
            for (int c = 0; c < 8; c++) {
                float x = pickhalf(acc2[r2][c], half) + bcol[c];
                ps += x;
                qs = fmaf(x, x, qs);
            }
#pragma unroll
            for (int off = 4; off <= 16; off <<= 1) {
                ps += __shfl_xor_sync(0xffffffffu, ps, off);
                qs += __shfl_xor_sync(0xffffffffu, qs, off);
            }
            if ((lane >> 2) == 0)
                red2[wcg * 128 + tRow + 2 * r2 + half] = make_float2(ps, qs);
        }
    __syncthreads();

    float mrow[4][2], irow[4][2];
#pragma unroll
    for (int r2 = 0; r2 < 4; r2++)
#pragma unroll
        for (int half = 0; half < 2; half++) {
            int lr = tRow + 2 * r2 + half;
            float2 a0 = red2[lr],       a1 = red2[128 + lr];
            float2 a2 = red2[256 + lr], a3 = red2[384 + lr];
            float sx = a0.x + a1.x + a2.x + a3.x;
            float sq = a0.y + a1.y + a2.y + a3.y;
            float m = sx * (1.f / 256.f);
            float var = sq * (1.f / 256.f) - m * m;
            mrow[r2][half] = m;
            irow[r2][half] = 1.f / sqrtf(var + 1e-5f);
        }

    float4 gg0 = *reinterpret_cast<const float4*>(&lng[tCol]);
    float4 gg1 = *reinterpret_cast<const float4*>(&lng[tCol + 4]);
    float4 ob0 = *reinterpret_cast<const float4*>(&lnb[tCol]);
    float4 ob1 = *reinterpret_cast<const float4*>(&lnb[tCol + 4]);
    float gcol[8] = {gg0.x, gg0.y, gg0.z, gg0.w, gg1.x, gg1.y, gg1.z, gg1.w};
    float ocol[8] = {ob0.x, ob0.y, ob0.z, ob0.w, ob1.x, ob1.y, ob1.z, ob1.w};

#pragma unroll
    for (int r2 = 0; r2 < 4; r2++) {
        float o2[2][8];
#pragma unroll
        for (int half = 0; half < 2; half++) {
            float m = mrow[r2][half];
            float inv = irow[r2][half];
#pragma unroll
            for (int c = 0; c < 8; c++) {
                float x = pickhalf(acc2[r2][c], half) + bcol[c];
                o2[half][c] = (x - m) * inv * gcol[c] + ocol[c];
            }
        }
#pragma unroll
        for (int half = 0; half < 2; half++) {
            int gr = rowBase + tRow + 2 * r2 + half;
            if (gr < MROWS) {
                float4 v0 = make_float4(o2[half][0], o2[half][1], o2[half][2], o2[half][3]);
                float4 v1 = make_float4(o2[half][4], o2[half][5], o2[half][6], o2[half][7]);
                *reinterpret_cast<float4*>(&Y[(size_t)gr * CH + tCol]) = v0;
                *reinterpret_cast<float4*>(&Y[(size_t)gr * CH + tCol + 4]) = v1;
            }
        }
        // LP smem: pair (row 2p, 2p+1) at block q=qA, slot j=r2, XOR-swizzled by k>>3
#pragma unroll
        for (int c = 0; c < 8; c++) {
            int k = tCol + c;
            int pp = ((qA ^ ((k >> 3) & 15)) << 2) | r2;
            *reinterpret_cast<float2*>(smf + LP_OFF + k * 136 + 2 * pp) =
                make_float2(o2[0][c], o2[1][c]);
        }
    }

    // ================= phase B: scores = rowmax(LP @ Wpad + bcls) ============
    __syncthreads();   // LP complete; phase-A As/Bs dead
    float* Ws  = smf;            // [buf][16][100] = 2*1600 floats
    float* redB = smf + GL_BS;   // [128][16]

    const int rowsB = (warp & 7) * 16 + (lane & 3) * 4;     // 4 rows per thread
    const int qB    = (warp & 7) * 2 + ((lane & 3) >> 1);
    const int jbase = ((lane & 3) & 1) * 2;
    const int tColB = (warp >> 3) * 48 + (lane >> 2) * 6;

    unsigned long long accB[2][6];
#pragma unroll
    for (int r = 0; r < 2; r++)
#pragma unroll
        for (int c = 0; c < 6; c++) accB[r][c] = 0ull;

    // fill slab 0
    for (int i = tid; i < 16 * NCP; i += 512)
        Ws[(i / NCP) * 100 + (i % NCP)] = Wp[i];
    __syncthreads();

#pragma unroll 1
    for (int sb = 0; sb < 16; sb++) {
        const int cur = sb & 1;
        float wr0 = 0.f, wr1 = 0.f, wr2 = 0.f;
        if (sb < 15) {
            const float* src = Wp + (sb + 1) * (16 * NCP);
            wr0 = src[tid]; wr1 = src[tid + 512]; wr2 = src[tid + 1024];
        }
        const float* Wc = Ws + cur * 1600;
#pragma unroll
        for (int kk = 0; kk < 16; kk++) {
            int k = sb * 16 + kk;
            int qx = qB ^ ((k >> 3) & 15);
            ulonglong2 av2 = *reinterpret_cast<const ulonglong2*>(
                smf + LP_OFF + k * 136 + 2 * ((qx << 2) + jbase));
            const float* brow = Wc + kk * 100 + tColB;
            float2 b01 = *reinterpret_cast<const float2*>(brow);
            float2 b23 = *reinterpret_cast<const float2*>(brow + 2);
            float2 b45 = *reinterpret_cast<const float2*>(brow + 4);
            unsigned long long av[2] = {av2.x, av2.y};
            float bf[6] = {b01.x, b01.y, b23.x, b23.y, b45.x, b45.y};
#pragma unroll
            for (int c = 0; c < 6; c++) {
                unsigned long long bc = bcast2(bf[c]);
                accB[0][c] = ffma2(av[0], bc, accB[0][c]);
                accB[1][c] = ffma2(av[1], bc, accB[1][c]);
            }
        }
        if (sb < 15) {
            float* Wn = Ws + (cur ^ 1) * 1600;
            Wn[(tid / NCP) * 100 + (tid % NCP)] = wr0;
            Wn[((tid + 512) / NCP) * 100 + ((tid + 512) % NCP)] = wr1;
            Wn[((tid + 1024) / NCP) * 100 + ((tid + 1024) % NCP)] = wr2;
        }
        __syncthreads();
    }

    // rowmax over this thread's 4 rows x 6 cols (+bias, guarded to gc<91)
    float mB[4] = {-INFINITY, -INFINITY, -INFINITY, -INFINITY};
#pragma unroll
    for (int r2 = 0; r2 < 2; r2++)
#pragma unroll
        for (int half = 0; half < 2; half++) {
            int r = 2 * r2 + half;
#pragma unroll
            for (int c = 0; c < 6; c++) {
                int gc = tColB + c;
                if (gc < NC)
                    mB[r] = fmaxf(mB[r], pickhalf(accB[r2][c], half) + bcls[gc]);
            }
        }
    const int slot = ((warp >> 3) << 3) | (lane >> 2);
#pragma unroll
    for (int r = 0; r < 4; r++)
        redB[(rowsB + r) * 16 + slot] = mB[r];
    __syncthreads();
    if (tid < 128) {
        int gr = rowBase + tid;
        if (gr < MROWS) {
            float m = -INFINITY;
#pragma unroll
            for (int s = 0; s < 16; s++) m = fmaxf(m, redB[tid * 16 + s]);
            scores[gr] = m;
        }
    }
}

// ============ top-k, two phase ==============================================
// Phase 1: register-resident values, 1 sync/iter, double-buffered broadcast.
__global__ void topk1_kernel(const float* __restrict__ scores,
                             float* __restrict__ candV, int* __restrict__ candI)
{
    const int c = blockIdx.x, b = blockIdx.y;
    const int base = c * CHUNK;
    const int cnt = min(CHUNK, SEQ - base);
    const int tid = threadIdx.x, lane = tid & 31, warp = tid >> 5;
    __shared__ float wv[2][8];
    __shared__ int   wi[2][8];

    float val[5];
#pragma unroll
    for (int j = 0; j < 5; j++) {
        int i = j * 256 + tid;
        val[j] = (i < cnt) ? scores[(size_t)b * SEQ + base + i] : -INFINITY;
    }

    for (int it = 0; it < NTOP; it++) {
        float bv = -INFINITY; int bi = 0x7fffffff;
#pragma unroll
        for (int j = 0; j < 5; j++) {
            if (val[j] > bv) { bv = val[j]; bi = j * 256 + tid; }
        }
#pragma unroll
        for (int off = 16; off; off >>= 1) {
            float ov = __shfl_xor_sync(0xffffffffu, bv, off);
            int   oi = __shfl_xor_sync(0xffffffffu, bi, off);
            if (ov > bv || (ov == bv && oi < bi)) { bv = ov; bi = oi; }
        }
        const int buf = it & 1;
        if (lane == 0) { wv[buf][warp] = bv; wi[buf][warp] = bi; }
        __syncthreads();
        // all warps reduce the 8 warp winners identically (lanes 0-7 active data)
        float fv = (lane < 8) ? wv[buf][lane] : -INFINITY;
        int   fi = (lane < 8) ? wi[buf][lane] : 0x7fffffff;
#pragma unroll
        for (int off = 4; off; off >>= 1) {
            float ov = __shfl_xor_sync(0xffffffffu, fv, off);
            int   oi = __shfl_xor_sync(0xffffffffu, fi, off);
            if (ov > fv || (ov == fv && oi < fi)) { fv = ov; fi = oi; }
        }
        fv = __shfl_sync(0xffffffffu, fv, 0);
        fi = __shfl_sync(0xffffffffu, fi, 0);
        if (tid == 0) {
            int o = (b * CHUNKS + c) * NTOP + it;
            candV[o] = fv; candI[o] = base + fi;
        }
        if ((fi & 255) == tid) {
            int jw = fi >> 8;
#pragma unroll
            for (int j = 0; j < 5; j++)
                if (j == jw) val[j] = -INFINITY;
        }
    }
}

// Phase 2: single warp, register-resident, sync-free shuffle extraction.
__global__ void topk2_kernel(const float* __restrict__ candV, const int* __restrict__ candI,
                             int* __restrict__ topIdx, float* __restrict__ topSc)
{
    const int b = blockIdx.x;
    const int lane = threadIdx.x;      // 32 threads
    const int NCAND = CHUNKS * NTOP;   // 320 = 10 per lane

    float v[10]; int gi[10];
#pragma unroll
    for (int j = 0; j < 10; j++) {
        int idx = j * 32 + lane;
        v[j]  = candV[b * NCAND + idx];
        gi[j] = candI[b * NCAND + idx];
    }

    for (int it = 0; it < NTOP; it++) {
        float bv = -INFINITY; int bgi = 0x7fffffff, bsl = 0, bow = lane;
#pragma unroll
        for (int j = 0; j < 10; j++) {
            if (v[j] > bv || (v[j] == bv && gi[j] < bgi)) {
                bv = v[j]; bgi = gi[j]; bsl = j;
            }
        }
#pragma unroll
        for (int off = 16; off; off >>= 1) {
            float ov = __shfl_xor_sync(0xffffffffu, bv, off);
            int  ogi = __shfl_xor_sync(0xffffffffu, bgi, off);
            int  osl = __shfl_xor_sync(0xffffffffu, bsl, off);
            int  oow = __shfl_xor_sync(0xffffffffu, bow, off);
            if (ov > bv || (ov == bv && ogi < bgi)) {
                bv = ov; bgi = ogi; bsl = osl; bow = oow;
            }
        }
        if (lane == 0) {
            topIdx[b * NTOP + it] = bgi;
            topSc[b * NTOP + it]  = bv;
        }
        if (lane == bow) {
#pragma unroll
            for (int j = 0; j < 10; j++)
                if (j == bsl) v[j] = -INFINITY;
        }
    }
}

// ---------------- tiny MLP + logits on top-k rows only -----------------------
__global__ void tinymlp_kernel(const float* __restrict__ outmem,
                               const unsigned char* __restrict__ mask,
                               const float* __restrict__ W1, const float* __restrict__ b1,
                               const float* __restrict__ W2, const float* __restrict__ b2,
                               const float* __restrict__ W3, const float* __restrict__ b3,
                               const float* __restrict__ Wc, const float* __restrict__ bcls,
                               const int* __restrict__ topIdx,
                               float* __restrict__ coordsTop,
                               float* __restrict__ topLog)
{
    __shared__ float s0[256], s1[256];
    const int blk = blockIdx.x;               // 0..159
    const int b = blk / NTOP;
    const int s = topIdx[blk];                // within-batch index
    const size_t row = (size_t)b * SEQ + s;
    const int tid = threadIdx.x;

    s0[tid] = outmem[row * CH + tid];
    __syncthreads();

    // logits for this row (threads 0..90): coalesced W_cls reads
    if (tid < NC) {
        float acc = bcls[tid];
#pragma unroll 8
        for (int kk = 0; kk < CH; kk++) acc = fmaf(s0[kk], Wc[kk * NC + tid], acc);
        topLog[blk * NC + tid] = acc;
    }

    float acc = 0.f;
#pragma unroll 8
    for (int kk = 0; kk < CH; kk++) acc = fmaf(s0[kk], W1[kk * CH + tid], acc);
    s1[tid] = fmaxf(acc + b1[tid], 0.f);
    __syncthreads();

    acc = 0.f;
#pragma unroll 8
    for (int kk = 0; kk < CH; kk++) acc = fmaf(s1[kk], W2[kk * CH + tid], acc);
    float h2 = fmaxf(acc + b2[tid], 0.f);
    __syncthreads();
    s0[tid] = h2;
    __syncthreads();

    const int warp = tid >> 5, lane = tid & 31;
    if (warp < 4) {
        float a = 0.f;
        for (int kk = lane; kk < CH; kk += 32)
            a = fmaf(s0[kk], W3[kk * 4 + warp], a);
#pragma unroll
        for (int off = 16; off; off >>= 1) a += __shfl_xor_sync(0xffffffffu, a, off);
        if (lane == 0) {
            int Hh, Ww, t;
            if (s < 15000)      { Hh = 100; Ww = 150; t = s; }
            else if (s < 18750) { Hh = 50;  Ww = 75;  t = s - 15000; }
            else if (s < 19700) { Hh = 25;  Ww = 38;  t = s - 18750; }
            else                { Hh = 13;  Ww = 19;  t = s - 19700; }
            int lvl = (s < 15000) ? 0 : (s < 18750) ? 1 : (s < 19700) ? 2 : 3;
            int y = t / Ww, x = t % Ww;
            float cx = ((float)x + 0.5f) / (float)Ww;
            float cy = ((float)y + 0.5f) / (float)Hh;
            float wh = 0.05f * (float)(1 << lvl);
            bool valid = (cx > 0.01f) && (cx < 0.99f) &&
                         (cy > 0.01f) && (cy < 0.99f);
            bool inv = (mask[row] != 0) || !valid;
            float pv;
            if (inv) pv = INFINITY;
            else {
                float comp = (warp == 0) ? cx : (warp == 1) ? cy : wh;
                pv = logf(comp / (1.f - comp));
            }
            coordsTop[blk * 4 + warp] = a + b3[warp] + pv;
        }
    }
}

// ---------------- final: gather + sigmoid + boxes + NMS ----------------------
__global__ void final_kernel(const float* __restrict__ topLog,
                             const float* __restrict__ coordsTop,
                             const int* __restrict__ topIdx, const float* __restrict__ topSc,
                             const float* __restrict__ WH, float* __restrict__ out)
{
    int b = blockIdx.x, tid = threadIdx.x;
    __shared__ float refp[NTOP][4];
    __shared__ float boxes[NTOP][4];

    for (int o = tid; o < NTOP * NC; o += blockDim.x) {
        int k = o / NC, c = o % NC;
        out[OFF_OUT + b * (NTOP * (NC + 4)) + k * (NC + 4) + c] =
            topLog[(b * NTOP + k) * NC + c];
    }
    if (tid < NTOP * 4) {
        int k = tid >> 2, c = tid & 3;
        float v = coordsTop[(b * NTOP + k) * 4 + c];
        out[OFF_OUT + b * (NTOP * (NC + 4)) + k * (NC + 4) + NC + c] = v;
        float r = 1.f / (1.f + expf(-v));
        out[OFF_REF + b * (NTOP * 4) + k * 4 + c] = r;
        refp[k][c] = r;
    }
    if (tid < NTOP) out[OFF_SC + b * NTOP + tid] = topSc[b * NTOP + tid];
    __syncthreads();
    if (tid < NTOP) {
        float cx = refp[tid][0], cy = refp[tid][1], w = refp[tid][2], h = refp[tid][3];
        boxes[tid][0] = truncf((cx - 0.5f * w) * WH[b * 4 + 0]);
        boxes[tid][1] = truncf((cy - 0.5f * h) * WH[b * 4 + 1]);
        boxes[tid][2] = truncf((cx + 0.5f * w) * WH[b * 4 + 2]);
        boxes[tid][3] = truncf((cy + 0.5f * h) * WH[b * 4 + 3]);
    }
    __syncthreads();
    if (tid == 0) {
        bool supp[NTOP];
        float area[NTOP];
        for (int k = 0; k < NTOP; k++) {
            supp[k] = false;
            area[k] = (boxes[k][2] - boxes[k][0]) * (boxes[k][3] - boxes[k][1]);
        }
        for (int i = 0; i < NTOP; i++) {
            if (supp[i]) continue;
            for (int j = i + 1; j < NTOP; j++) {
                float xx1 = fmaxf(boxes[i][0], boxes[j][0]);
                float yy1 = fmaxf(boxes[i][1], boxes[j][1]);
                float xx2 = fminf(boxes[i][2], boxes[j][2]);
                float yy2 = fminf(boxes[i][3], boxes[j][3]);
                float inter = fmaxf(xx2 - xx1, 0.f) * fmaxf(yy2 - yy1, 0.f);
                float iou = inter / (area[i] + area[j] - inter);
                if (iou > 0.5f) supp[j] = true;
            }
        }
        for (int k = 0; k < NTOP; k++)
            out[OFF_KEEP + b * NTOP + k] = supp[k] ? 0.f : 1.f;
    }
}

// ---------------- launch -----------------------------------------------------
extern "C" void kernel_launch(void* const* d_in, const int* in_sizes, int n_in,
                              void* d_out, int out_size)
{
    const float* memory        = (const float*)d_in[0];
    const unsigned char* mask  = (const unsigned char*)d_in[1];
    const float* WH            = (const float*)d_in[2];
    const float* W_enc         = (const float*)d_in[3];
    const float* b_enc         = (const float*)d_in[4];
    const float* ln_g          = (const float*)d_in[5];
    const float* ln_b          = (const float*)d_in[6];
    const float* W_cls         = (const float*)d_in[7];
    const float* b_cls         = (const float*)d_in[8];
    const float* W1            = (const float*)d_in[9];
    const float* b1            = (const float*)d_in[10];
    const float* W2            = (const float*)d_in[11];
    const float* b2            = (const float*)d_in[12];
    const float* W3            = (const float*)d_in[13];
    const float* b3            = (const float*)d_in[14];
    float* out = (float*)d_out;

    float *p_outmem, *p_scores, *p_topsc, *p_ctop, *p_candV, *p_wpad, *p_toplog;
    int *p_topidx, *p_candI;
    cudaGetSymbolAddress((void**)&p_outmem,  g_outmem);
    cudaGetSymbolAddress((void**)&p_scores,  g_scores);
    cudaGetSymbolAddress((void**)&p_topidx,  g_topidx);
    cudaGetSymbolAddress((void**)&p_topsc,   g_topsc);
    cudaGetSymbolAddress((void**)&p_ctop,    g_ctop);
    cudaGetSymbolAddress((void**)&p_candV,   g_candV);
    cudaGetSymbolAddress((void**)&p_candI,   g_candI);
    cudaGetSymbolAddress((void**)&p_wpad,    g_wpad);
    cudaGetSymbolAddress((void**)&p_toplog,  g_toplog);

    cudaFuncSetAttribute(gemm_fused_kernel,
                         cudaFuncAttributeMaxDynamicSharedMemorySize, GL_SMEM_BYTES);

    const int gRows = (MROWS + 127) / 128;   // 1247
    // pad W_cls -> [256][96]
    wpad_kernel<<<(CH * NCP + 255) / 256, 256>>>(W_cls, p_wpad);
    // out_mem = LN(mem_masked @ W_enc + b_enc); scores = rowmax(out_mem@Wcls+b)
    gemm_fused_kernel<<<gRows, 512, GL_SMEM_BYTES>>>(memory, mask, W_enc, b_enc,
                                                     ln_g, ln_b, p_wpad, b_cls,
                                                     p_outmem, p_scores);
    // top-20 per batch (two-phase)
    topk1_kernel<<<dim3(CHUNKS, BSZ), 256>>>(p_scores, p_candV, p_candI);
    topk2_kernel<<<BSZ, 32>>>(p_candV, p_candI, p_topidx, p_topsc);
    // MLP + coords + logits only on the 160 selected rows
    tinymlp_kernel<<<BSZ * NTOP, 256>>>(p_outmem, mask, W1, b1, W2, b2, W3, b3,
                                        W_cls, b_cls, p_topidx, p_ctop, p_toplog);
    // gather + sigmoid + NMS + writes
    final_kernel<<<BSZ, 128>>>(p_toplog, p_ctop, p_topidx, p_topsc, WH, out);

    (void)in_sizes; (void)n_in; (void)out_size;
}

// round 17
// speedup vs baseline: 1.0123x; 1.0123x over previous
#include <cuda_runtime.h>
#include <math.h>
#include <stdint.h>
#include <string.h>

#define BSZ   8
#define SEQ   19947
#define MROWS 159576          // BSZ*SEQ
#define CH    256
#define NC    91
#define NCP   96              // padded cls width
#define NTOP  20
#define CHUNKS 16
#define CHUNK  1247           // ceil(SEQ/16); last chunk = 1242

// output layout (float32, concatenated flattened tuple)
#define OFF_OUT  0            // (8,20,95)
#define OFF_REF  15200        // (8,20,4)
#define OFF_KEEP 15840        // (8,20)
#define OFF_SC   16000        // (8,20)

// ---------------- scratch (device globals: allocation-free) ----------------
__device__ float g_outmem[MROWS * CH];
__device__ float g_scores[MROWS];
__device__ int   g_topidx[BSZ * NTOP];
__device__ float g_topsc[BSZ * NTOP];
__device__ float g_ctop[BSZ * NTOP * 4];
__device__ float g_toplog[BSZ * NTOP * NC];
__device__ float g_candV[BSZ * CHUNKS * NTOP];
__device__ int   g_candI[BSZ * CHUNKS * NTOP];
__device__ float g_wpad[CH * NCP];        // W_cls padded to [256][96]

// ---------------- packed f32x2 helpers (Blackwell FFMA2) -------------------
__device__ __forceinline__ unsigned long long ffma2(unsigned long long a,
                                                    unsigned long long b,
                                                    unsigned long long c)
{
    unsigned long long d;
    asm("fma.rn.f32x2 %0, %1, %2, %3;" : "=l"(d) : "l"(a), "l"(b), "l"(c));
    return d;
}
__device__ __forceinline__ unsigned long long bcast2(float x)
{
    unsigned long long d;
    unsigned int xi = __float_as_uint(x);
    asm("mov.b64 %0, {%1, %1};" : "=l"(d) : "r"(xi));
    return d;
}
__device__ __forceinline__ float pickhalf(unsigned long long v, int half)
{
    float2 p;
    memcpy(&p, &v, 8);
    return half ? p.y : p.x;
}

// row validity by geometry + mask (reference _gen_proposals semantics)
__device__ __forceinline__ bool row_valid_geom(int s)
{
    int Hh, Ww, t;
    if (s < 15000)      { Hh = 100; Ww = 150; t = s; }
    else if (s < 18750) { Hh = 50;  Ww = 75;  t = s - 15000; }
    else if (s < 19700) { Hh = 25;  Ww = 38;  t = s - 18750; }
    else                { Hh = 13;  Ww = 19;  t = s - 19700; }
    int y = t / Ww, x = t % Ww;
    float cx = ((float)x + 0.5f) / (float)Ww;
    float cy = ((float)y + 0.5f) / (float)Hh;
    return (cx > 0.01f) && (cx < 0.99f) && (cy > 0.01f) && (cy < 0.99f);
}

// ---------------- pad W_cls [256][91] -> [256][96] ---------------------------
__global__ void wpad_kernel(const float* __restrict__ Wc, float* __restrict__ Wp)
{
    int idx = blockIdx.x * 256 + threadIdx.x;
    if (idx >= CH * NCP) return;
    int k = idx / NCP, n = idx % NCP;
    Wp[idx] = (n < NC) ? Wc[k * NC + n] : 0.f;
}

// ============ FUSED: GEMM1 + bias + LayerNorm + cls rowmax ===================
// Phase A: out_mem tile = LN(mem_masked @ W_enc + b_enc)  (write Y + smem LP)
// Phase B: scores[rows] = rowmax(LP @ Wpad + b_cls)       (A never re-read)
#define GL_AS 0
#define GL_BS 4224
#define LP_OFF 12928
#define GL_SMEM_FLOATS (12928 + 256 * 136)
#define GL_SMEM_BYTES (GL_SMEM_FLOATS * 4)

__global__ void __launch_bounds__(512, 1)
gemm_fused_kernel(const float* __restrict__ A, const unsigned char* __restrict__ mask,
                  const float* __restrict__ Bm, const float* __restrict__ bias,
                  const float* __restrict__ lng, const float* __restrict__ lnb,
                  const float* __restrict__ Wp, const float* __restrict__ bcls,
                  float* __restrict__ Y, float* __restrict__ scores)
{
    extern __shared__ float smf[];
    float* AsB = smf + GL_AS;     // [buf][16][132]
    float* BsB = smf + GL_BS;     // [buf][16][256]

    const int tid = threadIdx.x;
    const int warp = tid >> 5, lane = tid & 31;
    const int rowBase = blockIdx.x * 128;

    const int tRow = (warp & 3) * 32 + (lane & 3) * 8;
    const int tCol = (warp >> 2) * 64 + (lane >> 2) * 8;
    const int wcg  = warp >> 2;
    const int qA   = (warp & 3) * 4 + (lane & 3);   // pair-block id for LP writes

    const int aRow = tid >> 2, aK = (tid & 3) << 2;
    const int agr = rowBase + aRow;
    bool avalid = false;
    if (agr < MROWS) {
        int s = agr % SEQ;
        avalid = (mask[agr] == 0) && row_valid_geom(s);
    }
    const float* arow = A + (size_t)agr * CH;
    const int bK0 = tid >> 6, bN = (tid & 63) << 2, bK1 = bK0 + 8;

    unsigned long long acc2[4][8];
#pragma unroll
    for (int r = 0; r < 4; r++)
#pragma unroll
        for (int c = 0; c < 8; c++) acc2[r][c] = 0ull;

    float4 a0r = avalid ? *reinterpret_cast<const float4*>(arow + aK)
                        : make_float4(0.f, 0.f, 0.f, 0.f);
    float4 b0r = *reinterpret_cast<const float4*>(Bm + (size_t)bK0 * CH + bN);
    float4 b1r = *reinterpret_cast<const float4*>(Bm + (size_t)bK1 * CH + bN);
    AsB[(aK+0)*132 + aRow] = a0r.x; AsB[(aK+1)*132 + aRow] = a0r.y;
    AsB[(aK+2)*132 + aRow] = a0r.z; AsB[(aK+3)*132 + aRow] = a0r.w;
    *reinterpret_cast<float4*>(&BsB[bK0*256 + bN]) = b0r;
    *reinterpret_cast<float4*>(&BsB[bK1*256 + bN]) = b1r;
    __syncthreads();

#pragma unroll 1
    for (int kb = 0; kb < 16; kb++) {
        const int cur = kb & 1;
        float* As = AsB + cur * (16 * 132);
        float* Bs = BsB + cur * (16 * 256);
        if (kb < 15) {
            int k0 = (kb + 1) * 16;
            a0r = avalid ? *reinterpret_cast<const float4*>(arow + k0 + aK)
                         : make_float4(0.f, 0.f, 0.f, 0.f);
            b0r = *reinterpret_cast<const float4*>(Bm + (size_t)(k0 + bK0) * CH + bN);
            b1r = *reinterpret_cast<const float4*>(Bm + (size_t)(k0 + bK1) * CH + bN);
        }
#pragma unroll
        for (int kk = 0; kk < 16; kk++) {
            ulonglong2 a01 = *reinterpret_cast<const ulonglong2*>(&As[kk*132 + tRow]);
            ulonglong2 a23 = *reinterpret_cast<const ulonglong2*>(&As[kk*132 + tRow + 4]);
            float4 b0 = *reinterpret_cast<const float4*>(&Bs[kk*256 + tCol]);
            float4 b1 = *reinterpret_cast<const float4*>(&Bs[kk*256 + tCol + 4]);
            unsigned long long av[4] = {a01.x, a01.y, a23.x, a23.y};
            float bf[8] = {b0.x, b0.y, b0.z, b0.w, b1.x, b1.y, b1.z, b1.w};
#pragma unroll
            for (int c = 0; c < 8; c++) {
                unsigned long long bc = bcast2(bf[c]);
#pragma unroll
                for (int r = 0; r < 4; r++)
                    acc2[r][c] = ffma2(av[r], bc, acc2[r][c]);
            }
        }
        if (kb < 15) {
            float* Asn = AsB + (cur ^ 1) * (16 * 132);
            float* Bsn = BsB + (cur ^ 1) * (16 * 256);
            Asn[(aK+0)*132 + aRow] = a0r.x; Asn[(aK+1)*132 + aRow] = a0r.y;
            Asn[(aK+2)*132 + aRow] = a0r.z; Asn[(aK+3)*132 + aRow] = a0r.w;
            *reinterpret_cast<float4*>(&Bsn[bK0*256 + bN]) = b0r;
            *reinterpret_cast<float4*>(&Bsn[bK1*256 + bN]) = b1r;
            __syncthreads();
        }
    }

    // ---- phase A epilogue: bias + LayerNorm (single-pass sum/sumsq) ----
    float4 bb0 = *reinterpret_cast<const float4*>(&bias[tCol]);
    float4 bb1 = *reinterpret_cast<const float4*>(&bias[tCol + 4]);
    float bcol[8] = {bb0.x, bb0.y, bb0.z, bb0.w, bb1.x, bb1.y, bb1.z, bb1.w};

    __syncthreads();   // mainloop smem dead; reuse BsB region as float2[4][128]
    float2* red2 = reinterpret_cast<float2*>(smf + GL_BS);

#pragma unroll
    for (int r2 = 0; r2 < 4; r2++)
#pragma unroll
        for (int half = 0; half < 2; half++) {
            float ps = 0.f, qs = 0.f;
#pragma unroll
            for (int c = 0; c < 8; c++) {
                float x = pickhalf(acc2[r2][c], half) + bcol[c];
                ps += x;
                qs = fmaf(x, x, qs);
            }
#pragma unroll
            for (int off = 4; off <= 16; off <<= 1) {
                ps += __shfl_xor_sync(0xffffffffu, ps, off);
                qs += __shfl_xor_sync(0xffffffffu, qs, off);
            }
            if ((lane >> 2) == 0)
                red2[wcg * 128 + tRow + 2 * r2 + half] = make_float2(ps, qs);
        }
    __syncthreads();

    float mrow[4][2], irow[4][2];
#pragma unroll
    for (int r2 = 0; r2 < 4; r2++)
#pragma unroll
        for (int half = 0; half < 2; half++) {
            int lr = tRow + 2 * r2 + half;
            float2 a0 = red2[lr],       a1 = red2[128 + lr];
            float2 a2 = red2[256 + lr], a3 = red2[384 + lr];
            float sx = a0.x + a1.x + a2.x + a3.x;
            float sq = a0.y + a1.y + a2.y + a3.y;
            float m = sx * (1.f / 256.f);
            float var = sq * (1.f / 256.f) - m * m;
            mrow[r2][half] = m;
            irow[r2][half] = 1.f / sqrtf(var + 1e-5f);
        }

    float4 gg0 = *reinterpret_cast<const float4*>(&lng[tCol]);
    float4 gg1 = *reinterpret_cast<const float4*>(&lng[tCol + 4]);
    float4 ob0 = *reinterpret_cast<const float4*>(&lnb[tCol]);
    float4 ob1 = *reinterpret_cast<const float4*>(&lnb[tCol + 4]);
    float gcol[8] = {gg0.x, gg0.y, gg0.z, gg0.w, gg1.x, gg1.y, gg1.z, gg1.w};
    float ocol[8] = {ob0.x, ob0.y, ob0.z, ob0.w, ob1.x, ob1.y, ob1.z, ob1.w};

#pragma unroll
    for (int r2 = 0; r2 < 4; r2++) {
        float o2[2][8];
#pragma unroll
        for (int half = 0; half < 2; half++) {
            float m = mrow[r2][half];
            float inv = irow[r2][half];
#pragma unroll
            for (int c = 0; c < 8; c++) {
                float x = pickhalf(acc2[r2][c], half) + bcol[c];
                o2[half][c] = (x - m) * inv * gcol[c] + ocol[c];
            }
        }
#pragma unroll
        for (int half = 0; half < 2; half++) {
            int gr = rowBase + tRow + 2 * r2 + half;
            if (gr < MROWS) {
                float4 v0 = make_float4(o2[half][0], o2[half][1], o2[half][2], o2[half][3]);
                float4 v1 = make_float4(o2[half][4], o2[half][5], o2[half][6], o2[half][7]);
                *reinterpret_cast<float4*>(&Y[(size_t)gr * CH + tCol]) = v0;
                *reinterpret_cast<float4*>(&Y[(size_t)gr * CH + tCol + 4]) = v1;
            }
        }
        // LP smem: pair (row 2p, 2p+1) at block q=qA, slot j=r2, XOR-swizzled by k>>3
#pragma unroll
        for (int c = 0; c < 8; c++) {
            int k = tCol + c;
            int pp = ((qA ^ ((k >> 3) & 15)) << 2) | r2;
            *reinterpret_cast<float2*>(smf + LP_OFF + k * 136 + 2 * pp) =
                make_float2(o2[0][c], o2[1][c]);
        }
    }

    // ================= phase B: scores = rowmax(LP @ Wpad + bcls) ============
    // 32-k slabs, double-buffered Ws [buf][32][100], 8 syncs.
    __syncthreads();   // LP complete; phase-A As/Bs dead
    float* Ws   = smf;               // 2 * 3200 floats
    float* redB = smf + 6400;        // [128][16]

    const int rowsB = (warp & 7) * 16 + (lane & 3) * 4;     // 4 rows per thread
    const int qB    = (warp & 7) * 2 + ((lane & 3) >> 1);
    const int jbase = ((lane & 3) & 1) * 2;
    const int tColB = (warp >> 3) * 48 + (lane >> 2) * 6;

    unsigned long long accB[2][6];
#pragma unroll
    for (int r = 0; r < 2; r++)
#pragma unroll
        for (int c = 0; c < 6; c++) accB[r][c] = 0ull;

    // fill slab 0 (32 k-rows x 96 = 3072 contiguous floats)
#pragma unroll
    for (int j = 0; j < 6; j++) {
        int i = j * 512 + tid;
        Ws[(i / NCP) * 100 + (i % NCP)] = Wp[i];
    }
    __syncthreads();

#pragma unroll 1
    for (int sb = 0; sb < 8; sb++) {
        const int cur = sb & 1;
        float wr[6];
        if (sb < 7) {
            const float* src = Wp + (sb + 1) * (32 * NCP);
#pragma unroll
            for (int j = 0; j < 6; j++) wr[j] = src[j * 512 + tid];
        }
        const float* Wc = Ws + cur * 3200;
#pragma unroll
        for (int kk = 0; kk < 32; kk++) {
            int k = sb * 32 + kk;
            int qx = qB ^ ((k >> 3) & 15);
            ulonglong2 av2 = *reinterpret_cast<const ulonglong2*>(
                smf + LP_OFF + k * 136 + 2 * ((qx << 2) + jbase));
            const float* brow = Wc + kk * 100 + tColB;
            float2 b01 = *reinterpret_cast<const float2*>(brow);
            float2 b23 = *reinterpret_cast<const float2*>(brow + 2);
            float2 b45 = *reinterpret_cast<const float2*>(brow + 4);
            unsigned long long av[2] = {av2.x, av2.y};
            float bf[6] = {b01.x, b01.y, b23.x, b23.y, b45.x, b45.y};
#pragma unroll
            for (int c = 0; c < 6; c++) {
                unsigned long long bc = bcast2(bf[c]);
                accB[0][c] = ffma2(av[0], bc, accB[0][c]);
                accB[1][c] = ffma2(av[1], bc, accB[1][c]);
            }
        }
        if (sb < 7) {
            float* Wn = Ws + (cur ^ 1) * 3200;
#pragma unroll
            for (int j = 0; j < 6; j++) {
                int i = j * 512 + tid;
                Wn[(i / NCP) * 100 + (i % NCP)] = wr[j];
            }
        }
        __syncthreads();
    }

    // rowmax over this thread's 4 rows x 6 cols (+bias, guarded to gc<91)
    float mB[4] = {-INFINITY, -INFINITY, -INFINITY, -INFINITY};
#pragma unroll
    for (int r2 = 0; r2 < 2; r2++)
#pragma unroll
        for (int half = 0; half < 2; half++) {
            int r = 2 * r2 + half;
#pragma unroll
            for (int c = 0; c < 6; c++) {
                int gc = tColB + c;
                if (gc < NC)
                    mB[r] = fmaxf(mB[r], pickhalf(accB[r2][c], half) + bcls[gc]);
            }
        }
    const int slot = ((warp >> 3) << 3) | (lane >> 2);
#pragma unroll
    for (int r = 0; r < 4; r++)
        redB[(rowsB + r) * 16 + slot] = mB[r];
    __syncthreads();
    if (tid < 128) {
        int gr = rowBase + tid;
        if (gr < MROWS) {
            float m = -INFINITY;
#pragma unroll
            for (int s = 0; s < 16; s++) m = fmaxf(m, redB[tid * 16 + s]);
            scores[gr] = m;
        }
    }
}

// ============ top-k, two phase ==============================================
// Phase 1: register-resident values, 1 sync/iter, double-buffered broadcast.
__global__ void topk1_kernel(const float* __restrict__ scores,
                             float* __restrict__ candV, int* __restrict__ candI)
{
    const int c = blockIdx.x, b = blockIdx.y;
    const int base = c * CHUNK;
    const int cnt = min(CHUNK, SEQ - base);
    const int tid = threadIdx.x, lane = tid & 31, warp = tid >> 5;
    __shared__ float wv[2][8];
    __shared__ int   wi[2][8];

    float val[5];
#pragma unroll
    for (int j = 0; j < 5; j++) {
        int i = j * 256 + tid;
        val[j] = (i < cnt) ? scores[(size_t)b * SEQ + base + i] : -INFINITY;
    }

    for (int it = 0; it < NTOP; it++) {
        float bv = -INFINITY; int bi = 0x7fffffff;
#pragma unroll
        for (int j = 0; j < 5; j++) {
            if (val[j] > bv) { bv = val[j]; bi = j * 256 + tid; }
        }
#pragma unroll
        for (int off = 16; off; off >>= 1) {
            float ov = __shfl_xor_sync(0xffffffffu, bv, off);
            int   oi = __shfl_xor_sync(0xffffffffu, bi, off);
            if (ov > bv || (ov == bv && oi < bi)) { bv = ov; bi = oi; }
        }
        const int buf = it & 1;
        if (lane == 0) { wv[buf][warp] = bv; wi[buf][warp] = bi; }
        __syncthreads();
        float fv = (lane < 8) ? wv[buf][lane] : -INFINITY;
        int   fi = (lane < 8) ? wi[buf][lane] : 0x7fffffff;
#pragma unroll
        for (int off = 4; off; off >>= 1) {
            float ov = __shfl_xor_sync(0xffffffffu, fv, off);
            int   oi = __shfl_xor_sync(0xffffffffu, fi, off);
            if (ov > fv || (ov == fv && oi < fi)) { fv = ov; fi = oi; }
        }
        fv = __shfl_sync(0xffffffffu, fv, 0);
        fi = __shfl_sync(0xffffffffu, fi, 0);
        if (tid == 0) {
            int o = (b * CHUNKS + c) * NTOP + it;
            candV[o] = fv; candI[o] = base + fi;
        }
        if ((fi & 255) == tid) {
            int jw = fi >> 8;
#pragma unroll
            for (int j = 0; j < 5; j++)
                if (j == jw) val[j] = -INFINITY;
        }
    }
}

// Phase 2: 320 threads (measured-fastest variant).
__global__ void topk2_kernel(const float* __restrict__ candV, const int* __restrict__ candI,
                             int* __restrict__ topIdx, float* __restrict__ topSc)
{
    const int b = blockIdx.x;
    const int NCAND = CHUNKS * NTOP;       // 320
    __shared__ float cv[NCAND];
    __shared__ int   ci[NCAND];
    __shared__ float wv[10];
    __shared__ int   wgi[10], wps[10];
    const int tid = threadIdx.x, lane = tid & 31, warp = tid >> 5;

    if (tid < NCAND) { cv[tid] = candV[b * NCAND + tid]; ci[tid] = candI[b * NCAND + tid]; }
    __syncthreads();

    for (int it = 0; it < NTOP; it++) {
        float v = (tid < NCAND) ? cv[tid] : -INFINITY;
        int gi = (tid < NCAND) ? ci[tid] : 0x7fffffff;
        int ps = tid;
#pragma unroll
        for (int off = 16; off; off >>= 1) {
            float ov = __shfl_xor_sync(0xffffffffu, v, off);
            int  ogi = __shfl_xor_sync(0xffffffffu, gi, off);
            int  ops = __shfl_xor_sync(0xffffffffu, ps, off);
            if (ov > v || (ov == v && ogi < gi)) { v = ov; gi = ogi; ps = ops; }
        }
        if (lane == 0) { wv[warp] = v; wgi[warp] = gi; wps[warp] = ps; }
        __syncthreads();
        if (tid == 0) {
            float fv = wv[0]; int fgi = wgi[0], fps = wps[0];
#pragma unroll
            for (int w = 1; w < 10; w++)
                if (wv[w] > fv || (wv[w] == fv && wgi[w] < fgi)) {
                    fv = wv[w]; fgi = wgi[w]; fps = wps[w];
                }
            topIdx[b * NTOP + it] = fgi;
            topSc[b * NTOP + it]  = fv;
            cv[fps] = -INFINITY;
        }
        __syncthreads();
    }
}

// ---------------- tiny MLP + logits on top-k rows only -----------------------
__global__ void tinymlp_kernel(const float* __restrict__ outmem,
                               const unsigned char* __restrict__ mask,
                               const float* __restrict__ W1, const float* __restrict__ b1,
                               const float* __restrict__ W2, const float* __restrict__ b2,
                               const float* __restrict__ W3, const float* __restrict__ b3,
                               const float* __restrict__ Wc, const float* __restrict__ bcls,
                               const int* __restrict__ topIdx,
                               float* __restrict__ coordsTop,
                               float* __restrict__ topLog)
{
    __shared__ float s0[256], s1[256];
    const int blk = blockIdx.x;               // 0..159
    const int b = blk / NTOP;
    const int s = topIdx[blk];                // within-batch index
    const size_t row = (size_t)b * SEQ + s;
    const int tid = threadIdx.x;

    s0[tid] = outmem[row * CH + tid];
    __syncthreads();

    // logits for this row (threads 0..90): 4 independent accumulator chains
    if (tid < NC) {
        float a0 = bcls[tid], a1 = 0.f, a2 = 0.f, a3 = 0.f;
#pragma unroll 4
        for (int kk = 0; kk < CH; kk += 4) {
            a0 = fmaf(s0[kk+0], Wc[(kk+0) * NC + tid], a0);
            a1 = fmaf(s0[kk+1], Wc[(kk+1) * NC + tid], a1);
            a2 = fmaf(s0[kk+2], Wc[(kk+2) * NC + tid], a2);
            a3 = fmaf(s0[kk+3], Wc[(kk+3) * NC + tid], a3);
        }
        topLog[blk * NC + tid] = (a0 + a1) + (a2 + a3);
    }

    {
        float a0 = 0.f, a1 = 0.f, a2 = 0.f, a3 = 0.f;
#pragma unroll 4
        for (int kk = 0; kk < CH; kk += 4) {
            a0 = fmaf(s0[kk+0], W1[(kk+0) * CH + tid], a0);
            a1 = fmaf(s0[kk+1], W1[(kk+1) * CH + tid], a1);
            a2 = fmaf(s0[kk+2], W1[(kk+2) * CH + tid], a2);
            a3 = fmaf(s0[kk+3], W1[(kk+3) * CH + tid], a3);
        }
        s1[tid] = fmaxf((a0 + a1) + (a2 + a3) + b1[tid], 0.f);
    }
    __syncthreads();

    float h2;
    {
        float a0 = 0.f, a1 = 0.f, a2 = 0.f, a3 = 0.f;
#pragma unroll 4
        for (int kk = 0; kk < CH; kk += 4) {
            a0 = fmaf(s1[kk+0], W2[(kk+0) * CH + tid], a0);
            a1 = fmaf(s1[kk+1], W2[(kk+1) * CH + tid], a1);
            a2 = fmaf(s1[kk+2], W2[(kk+2) * CH + tid], a2);
            a3 = fmaf(s1[kk+3], W2[(kk+3) * CH + tid], a3);
        }
        h2 = fmaxf((a0 + a1) + (a2 + a3) + b2[tid], 0.f);
    }
    __syncthreads();
    s0[tid] = h2;
    __syncthreads();

    const int warp = tid >> 5, lane = tid & 31;
    if (warp < 4) {
        float a = 0.f;
        for (int kk = lane; kk < CH; kk += 32)
            a = fmaf(s0[kk], W3[kk * 4 + warp], a);
#pragma unroll
        for (int off = 16; off; off >>= 1) a += __shfl_xor_sync(0xffffffffu, a, off);
        if (lane == 0) {
            int Hh, Ww, t;
            if (s < 15000)      { Hh = 100; Ww = 150; t = s; }
            else if (s < 18750) { Hh = 50;  Ww = 75;  t = s - 15000; }
            else if (s < 19700) { Hh = 25;  Ww = 38;  t = s - 18750; }
            else                { Hh = 13;  Ww = 19;  t = s - 19700; }
            int lvl = (s < 15000) ? 0 : (s < 18750) ? 1 : (s < 19700) ? 2 : 3;
            int y = t / Ww, x = t % Ww;
            float cx = ((float)x + 0.5f) / (float)Ww;
            float cy = ((float)y + 0.5f) / (float)Hh;
            float wh = 0.05f * (float)(1 << lvl);
            bool valid = (cx > 0.01f) && (cx < 0.99f) &&
                         (cy > 0.01f) && (cy < 0.99f);
            bool inv = (mask[row] != 0) || !valid;
            float pv;
            if (inv) pv = INFINITY;
            else {
                float comp = (warp == 0) ? cx : (warp == 1) ? cy : wh;
                pv = logf(comp / (1.f - comp));
            }
            coordsTop[blk * 4 + warp] = a + b3[warp] + pv;
        }
    }
}

// ---------------- final: gather + sigmoid + boxes + NMS ----------------------
__global__ void final_kernel(const float* __restrict__ topLog,
                             const float* __restrict__ coordsTop,
                             const int* __restrict__ topIdx, const float* __restrict__ topSc,
                             const float* __restrict__ WH, float* __restrict__ out)
{
    int b = blockIdx.x, tid = threadIdx.x;
    __shared__ float refp[NTOP][4];
    __shared__ float boxes[NTOP][4];

    for (int o = tid; o < NTOP * NC; o += blockDim.x) {
        int k = o / NC, c = o % NC;
        out[OFF_OUT + b * (NTOP * (NC + 4)) + k * (NC + 4) + c] =
            topLog[(b * NTOP + k) * NC + c];
    }
    if (tid < NTOP * 4) {
        int k = tid >> 2, c = tid & 3;
        float v = coordsTop[(b * NTOP + k) * 4 + c];
        out[OFF_OUT + b * (NTOP * (NC + 4)) + k * (NC + 4) + NC + c] = v;
        float r = 1.f / (1.f + expf(-v));
        out[OFF_REF + b * (NTOP * 4) + k * 4 + c] = r;
        refp[k][c] = r;
    }
    if (tid < NTOP) out[OFF_SC + b * NTOP + tid] = topSc[b * NTOP + tid];
    __syncthreads();
    if (tid < NTOP) {
        float cx = refp[tid][0], cy = refp[tid][1], w = refp[tid][2], h = refp[tid][3];
        boxes[tid][0] = truncf((cx - 0.5f * w) * WH[b * 4 + 0]);
        boxes[tid][1] = truncf((cy - 0.5f * h) * WH[b * 4 + 1]);
        boxes[tid][2] = truncf((cx + 0.5f * w) * WH[b * 4 + 2]);
        boxes[tid][3] = truncf((cy + 0.5f * h) * WH[b * 4 + 3]);
    }
    __syncthreads();
    if (tid == 0) {
        bool supp[NTOP];
        float area[NTOP];
        for (int k = 0; k < NTOP; k++) {
            supp[k] = false;
            area[k] = (boxes[k][2] - boxes[k][0]) * (boxes[k][3] - boxes[k][1]);
        }
        for (int i = 0; i < NTOP; i++) {
            if (supp[i]) continue;
            for (int j = i + 1; j < NTOP; j++) {
                float xx1 = fmaxf(boxes[i][0], boxes[j][0]);
                float yy1 = fmaxf(boxes[i][1], boxes[j][1]);
                float xx2 = fminf(boxes[i][2], boxes[j][2]);
                float yy2 = fminf(boxes[i][3], boxes[j][3]);
                float inter = fmaxf(xx2 - xx1, 0.f) * fmaxf(yy2 - yy1, 0.f);
                float iou = inter / (area[i] + area[j] - inter);
                if (iou > 0.5f) supp[j] = true;
            }
        }
        for (int k = 0; k < NTOP; k++)
            out[OFF_KEEP + b * NTOP + k] = supp[k] ? 0.f : 1.f;
    }
}

// ---------------- launch -----------------------------------------------------
extern "C" void kernel_launch(void* const* d_in, const int* in_sizes, int n_in,
                              void* d_out, int out_size)
{
    const float* memory        = (const float*)d_in[0];
    const unsigned char* mask  = (const unsigned char*)d_in[1];
    const float* WH            = (const float*)d_in[2];
    const float* W_enc         = (const float*)d_in[3];
    const float* b_enc         = (const float*)d_in[4];
    const float* ln_g          = (const float*)d_in[5];
    const float* ln_b          = (const float*)d_in[6];
    const float* W_cls         = (const float*)d_in[7];
    const float* b_cls         = (const float*)d_in[8];
    const float* W1            = (const float*)d_in[9];
    const float* b1            = (const float*)d_in[10];
    const float* W2            = (const float*)d_in[11];
    const float* b2            = (const float*)d_in[12];
    const float* W3            = (const float*)d_in[13];
    const float* b3            = (const float*)d_in[14];
    float* out = (float*)d_out;

    float *p_outmem, *p_scores, *p_topsc, *p_ctop, *p_candV, *p_wpad, *p_toplog;
    int *p_topidx, *p_candI;
    cudaGetSymbolAddress((void**)&p_outmem,  g_outmem);
    cudaGetSymbolAddress((void**)&p_scores,  g_scores);
    cudaGetSymbolAddress((void**)&p_topidx,  g_topidx);
    cudaGetSymbolAddress((void**)&p_topsc,   g_topsc);
    cudaGetSymbolAddress((void**)&p_ctop,    g_ctop);
    cudaGetSymbolAddress((void**)&p_candV,   g_candV);
    cudaGetSymbolAddress((void**)&p_candI,   g_candI);
    cudaGetSymbolAddress((void**)&p_wpad,    g_wpad);
    cudaGetSymbolAddress((void**)&p_toplog,  g_toplog);

    cudaFuncSetAttribute(gemm_fused_kernel,
                         cudaFuncAttributeMaxDynamicSharedMemorySize, GL_SMEM_BYTES);

    const int gRows = (MROWS + 127) / 128;   // 1247
    // pad W_cls -> [256][96]
    wpad_kernel<<<(CH * NCP + 255) / 256, 256>>>(W_cls, p_wpad);
    // out_mem = LN(mem_masked @ W_enc + b_enc); scores = rowmax(out_mem@Wcls+b)
    gemm_fused_kernel<<<gRows, 512, GL_SMEM_BYTES>>>(memory, mask, W_enc, b_enc,
                                                     ln_g, ln_b, p_wpad, b_cls,
                                                     p_outmem, p_scores);
    // top-20 per batch (two-phase)
    topk1_kernel<<<dim3(CHUNKS, BSZ), 256>>>(p_scores, p_candV, p_candI);
    topk2_kernel<<<BSZ, 320>>>(p_candV, p_candI, p_topidx, p_topsc);
    // MLP + coords + logits only on the 160 selected rows
    tinymlp_kernel<<<BSZ * NTOP, 256>>>(p_outmem, mask, W1, b1, W2, b2, W3, b3,
                                        W_cls, b_cls, p_topidx, p_ctop, p_toplog);
    // gather + sigmoid + NMS + writes
    final_kernel<<<BSZ, 128>>>(p_toplog, p_ctop, p_topidx, p_topsc, WH, out);

    (void)in_sizes; (void)n_in; (void)out_size;
}